// round 8
// baseline (speedup 1.0000x reference)
#include <cuda_runtime.h>
#include <cuda_bf16.h>

// Problem constants
#define BB 2
#define SS 2048
#define DD 128
#define HH 8
#define HDIM 16
#define DFF 512
#define MROWS (BB*SS)     // 4096
#define DCAT 256          // concat width of [attn1 | attn2]

// ---------------- scratch (device globals; no allocation allowed) -------------
__device__ float g_q1[BB*HH*SS*HDIM];
__device__ float g_k1[BB*HH*SS*HDIM];
__device__ float g_v1[BB*HH*SS*HDIM];
__device__ float g_q2[BB*HH*SS*HDIM];
__device__ float g_k2[BB*HH*SS*HDIM];
__device__ float g_v2[BB*HH*SS*HDIM];
__device__ float g_attn_cat[MROWS*DCAT];   // [row][0:128]=self, [128:256]=cross
__device__ float g_r2[BB*SS*DD];
__device__ float2 g_stats[MROWS];          // per-row {mean, 127/ss} for LN
__device__ float g_h[BB*SS*DFF];

// ---------------- helpers -----------------------------------------------------
__device__ __forceinline__ unsigned pack_bf16x2(float lo, float hi) {
    unsigned r;
    asm("cvt.rn.bf16x2.f32 %0, %1, %2;" : "=r"(r) : "f"(hi), "f"(lo));
    return r;
}
__device__ __forceinline__ float ex2(float x) {
    float y;
    asm("ex2.approx.ftz.f32 %0, %1;" : "=f"(y) : "f"(x));
    return y;
}
// exp2 on the fma/alu pipes (MUFU offload). Magic-number round-to-nearest,
// degree-5 Taylor on f in [-0.5, 0.5] (rel err ~2e-6), scale via exponent add.
__device__ __forceinline__ float exp2_poly(float x) {
    float z = x + 12582912.0f;             // 1.5 * 2^23
    int ib = __float_as_int(z);            // low bits hold round(x)
    float nf = z - 12582912.0f;
    float f = x - nf;                      // [-0.5, 0.5]
    float p = 1.3333558146e-3f;
    p = fmaf(p, f, 9.6181291076e-3f);
    p = fmaf(p, f, 5.5504108664e-2f);
    p = fmaf(p, f, 2.4022650696e-1f);
    p = fmaf(p, f, 6.9314718056e-1f);
    p = fmaf(p, f, 1.0f);
    return __int_as_float(__float_as_int(p) + (ib << 23));  // * 2^n
}
__device__ __forceinline__ unsigned tf32(float x) {
    unsigned r;
    asm("cvt.rna.tf32.f32 %0, %1;" : "=r"(r) : "f"(x));
    return r;
}
__device__ __forceinline__ void mma_bf16(
    float& c0, float& c1, float& c2, float& c3,
    unsigned a0, unsigned a1, unsigned a2, unsigned a3,
    unsigned b0, unsigned b1)
{
    asm("mma.sync.aligned.m16n8k16.row.col.f32.bf16.bf16.f32 "
        "{%0,%1,%2,%3},{%4,%5,%6,%7},{%8,%9},{%0,%1,%2,%3};"
        : "+f"(c0), "+f"(c1), "+f"(c2), "+f"(c3)
        : "r"(a0), "r"(a1), "r"(a2), "r"(a3), "r"(b0), "r"(b1));
}
__device__ __forceinline__ void mma_tf32(
    float& c0, float& c1, float& c2, float& c3,
    unsigned a0, unsigned a1, unsigned a2, unsigned a3,
    unsigned b0, unsigned b1)
{
    asm("mma.sync.aligned.m16n8k8.row.col.f32.tf32.tf32.f32 "
        "{%0,%1,%2,%3},{%4,%5,%6,%7},{%8,%9},{%0,%1,%2,%3};"
        : "+f"(c0), "+f"(c1), "+f"(c2), "+f"(c3)
        : "r"(a0), "r"(a1), "r"(a2), "r"(a3), "r"(b0), "r"(b1));
}
__device__ __forceinline__ void cp16(unsigned dst, const void* src) {
    asm volatile("cp.async.cg.shared.global [%0], [%1], 16;"
                 :: "r"(dst), "l"(src));
}
__device__ __forceinline__ void cp_commit() {
    asm volatile("cp.async.commit_group;");
}
__device__ __forceinline__ void cp_wait1() {
    asm volatile("cp.async.wait_group 1;");
}

#define ASTR 20           // A-tile smem stride (words): 20g+t conflict-free
#define ATILE (64*ASTR)   // one A stage, words

// ---------------- cp.async-pipelined W-resident tf32 GEMM ---------------------
// out = A(MxK) @ W(KxN) + epilogue.  256 thr, 8 warps: 4 in M x 2 in N.
// W panel (K x BN) smem-resident (tf32, stride BN+8); A tiles (64x16 fp32)
// double-buffered via cp.async.
// EPI: 1 = +bias+res   2 = relu(+bias)   3 = fused r2 (W rows>=128 from W2,
//      out = acc + bias + bias2 + res)
// LNA: apply per-row layernorm (x - stats.x) * stats.y to A at fragment load.
template<int K, int N, int BN, int EPI, int LNA>
__global__ void __launch_bounds__(256) gemm_pipe_kernel(
    const float* __restrict__ A, const float* __restrict__ W,
    const float* __restrict__ W2,
    const float* __restrict__ bias, const float* __restrict__ bias2,
    const float* __restrict__ res, const float2* __restrict__ stats,
    float* __restrict__ out)
{
    constexpr int WSTR = BN + 8;
    constexpr int NT = BN / 16;          // n-tiles per warp
    constexpr int KT = K / 16;
    extern __shared__ unsigned smem[];
    unsigned* Ws = smem;                       // [K][WSTR] tf32
    float* As = (float*)(smem + K * WSTR);     // 2 x [64][ASTR] fp32
    const unsigned As_sh = (unsigned)__cvta_generic_to_shared(As);
    const int tid = threadIdx.x, warp = tid >> 5, lane = tid & 31;
    const int warp_m = warp >> 1, warp_n = warp & 1;
    const int g = lane >> 2, t = lane & 3;
    const int bm = blockIdx.y * 64, bn = blockIdx.x * BN;

    // stage whole weight panel (fp32 -> tf32), once
    for (int i = tid; i < K * (BN / 4); i += 256) {
        int row = i / (BN / 4), c = (i % (BN / 4)) * 4;
        float4 w4;
        if (EPI == 3 && row >= 128)
            w4 = *(const float4*)&W2[(size_t)(row - 128) * N + bn + c];
        else
            w4 = *(const float4*)&W[(size_t)row * N + bn + c];
        uint4 u = {tf32(w4.x), tf32(w4.y), tf32(w4.z), tf32(w4.w)};
        *(uint4*)&Ws[row * WSTR + c] = u;
    }

    // A prefetch: 64 rows x 16 k = 256 x 16B chunks, 1 per thread
    auto loadA = [&](int kt, int buf) {
        int row = tid >> 2, kc = (tid & 3) * 4;
        cp16(As_sh + (buf * ATILE + row * ASTR + kc) * 4,
             &A[(size_t)(bm + row) * K + kt * 16 + kc]);
        cp_commit();
    };
    loadA(0, 0);

    float acc[NT][4] = {};
    const int ra = warp_m * 16 + g;
    const int noff = warp_n * (BN / 2);

    float m0 = 0.f, i0 = 1.f, m1 = 0.f, i1 = 1.f;
    if (LNA) {
        float2 s0 = stats[bm + ra];
        float2 s1 = stats[bm + ra + 8];
        m0 = s0.x; i0 = s0.y; m1 = s1.x; i1 = s1.y;
    }

    for (int kt = 0; kt < KT; kt++) {
        if (kt + 1 < KT) loadA(kt + 1, (kt + 1) & 1);
        else cp_commit();                      // keep wait-group count aligned
        cp_wait1();
        __syncthreads();
        const float* Ab = As + (kt & 1) * ATILE;
#pragma unroll
        for (int kh = 0; kh < 16; kh += 8) {
            unsigned a0, a1, a2, a3;
            if (LNA) {
                a0 = tf32((Ab[ra * ASTR + kh + t] - m0) * i0);
                a1 = tf32((Ab[(ra + 8) * ASTR + kh + t] - m1) * i1);
                a2 = tf32((Ab[ra * ASTR + kh + t + 4] - m0) * i0);
                a3 = tf32((Ab[(ra + 8) * ASTR + kh + t + 4] - m1) * i1);
            } else {
                a0 = tf32(Ab[ra * ASTR + kh + t]);
                a1 = tf32(Ab[(ra + 8) * ASTR + kh + t]);
                a2 = tf32(Ab[ra * ASTR + kh + t + 4]);
                a3 = tf32(Ab[(ra + 8) * ASTR + kh + t + 4]);
            }
            const int kr = kt * 16 + kh;
#pragma unroll
            for (int j = 0; j < NT; j++) {
                unsigned b0 = Ws[(kr + t) * WSTR + noff + j * 8 + g];
                unsigned b1 = Ws[(kr + t + 4) * WSTR + noff + j * 8 + g];
                mma_tf32(acc[j][0], acc[j][1], acc[j][2], acc[j][3],
                         a0, a1, a2, a3, b0, b1);
            }
        }
        __syncthreads();
    }

    const int r0 = bm + ra;
#pragma unroll
    for (int j = 0; j < NT; j++) {
        int c0 = bn + noff + j * 8 + 2 * t;
        if (EPI == 1 || EPI == 3) {
            float2 bi = *(const float2*)&bias[c0];
            if (EPI == 3) {
                float2 bi2 = *(const float2*)&bias2[c0];
                bi.x += bi2.x; bi.y += bi2.y;
            }
            float2 rA = *(const float2*)&res[(size_t)r0 * N + c0];
            float2 rB = *(const float2*)&res[(size_t)(r0 + 8) * N + c0];
            float2 oA = {acc[j][0] + bi.x + rA.x, acc[j][1] + bi.y + rA.y};
            float2 oB = {acc[j][2] + bi.x + rB.x, acc[j][3] + bi.y + rB.y};
            *(float2*)&out[(size_t)r0 * N + c0] = oA;
            *(float2*)&out[(size_t)(r0 + 8) * N + c0] = oB;
        } else {
            float2 bi = *(const float2*)&bias[c0];
            float2 oA = {fmaxf(acc[j][0] + bi.x, 0.f), fmaxf(acc[j][1] + bi.y, 0.f)};
            float2 oB = {fmaxf(acc[j][2] + bi.x, 0.f), fmaxf(acc[j][3] + bi.y, 0.f)};
            *(float2*)&out[(size_t)r0 * N + c0] = oA;
            *(float2*)&out[(size_t)(r0 + 8) * N + c0] = oB;
        }
    }
}

// ---------------- ALL-SIX QKV projections in one launch (pipelined) -----------
// grid (12, 64), 256 thr/8 warps: blockIdx.x>>1 = {sq, sk, sv, cq, ck, cv}
// (cross Q reads enc_out — the reference's quirk).  Scatter col c ->
// h=c&7, hd=c>>3 into [b][h][s][hd].
__global__ void __launch_bounds__(256) gemm_qkv6_kernel(
    const float* __restrict__ x_tgt, const float* __restrict__ enc,
    const float* __restrict__ swq, const float* __restrict__ swk,
    const float* __restrict__ swv, const float* __restrict__ cwq,
    const float* __restrict__ cwk, const float* __restrict__ cwv,
    float* __restrict__ q1, float* __restrict__ k1, float* __restrict__ v1,
    float* __restrict__ q2, float* __restrict__ k2, float* __restrict__ v2)
{
    const int which = blockIdx.x >> 1;
    const float* A = (which == 3) ? enc : x_tgt;
    const float* W; float* out;
    switch (which) {
        case 0: W = swq; out = q1; break;
        case 1: W = swk; out = k1; break;
        case 2: W = swv; out = v1; break;
        case 3: W = cwq; out = q2; break;
        case 4: W = cwk; out = k2; break;
        default: W = cwv; out = v2; break;
    }

    constexpr int WSTR = 72;
    extern __shared__ unsigned smem[];
    unsigned* Ws = smem;                       // [128][72]
    float* As = (float*)(smem + DD * WSTR);
    const unsigned As_sh = (unsigned)__cvta_generic_to_shared(As);
    const int tid = threadIdx.x, warp = tid >> 5, lane = tid & 31;
    const int warp_m = warp >> 1, warp_n = warp & 1;
    const int g = lane >> 2, t = lane & 3;
    const int bm = blockIdx.y * 64, bn = (blockIdx.x & 1) * 64;

    for (int i = tid; i < DD * 16; i += 256) {
        int row = i / 16, c = (i % 16) * 4;
        float4 w4 = *(const float4*)&W[(size_t)row * DD + bn + c];
        uint4 u = {tf32(w4.x), tf32(w4.y), tf32(w4.z), tf32(w4.w)};
        *(uint4*)&Ws[row * WSTR + c] = u;
    }

    auto loadA = [&](int kt, int buf) {
        int row = tid >> 2, kc = (tid & 3) * 4;
        cp16(As_sh + (buf * ATILE + row * ASTR + kc) * 4,
             &A[(size_t)(bm + row) * DD + kt * 16 + kc]);
        cp_commit();
    };
    loadA(0, 0);

    float acc[4][4] = {};
    const int ra = warp_m * 16 + g;
    const int noff = warp_n * 32;

    for (int kt = 0; kt < DD / 16; kt++) {
        if (kt + 1 < DD / 16) loadA(kt + 1, (kt + 1) & 1);
        else cp_commit();
        cp_wait1();
        __syncthreads();
        const float* Ab = As + (kt & 1) * ATILE;
#pragma unroll
        for (int kh = 0; kh < 16; kh += 8) {
            unsigned a0 = tf32(Ab[ra * ASTR + kh + t]);
            unsigned a1 = tf32(Ab[(ra + 8) * ASTR + kh + t]);
            unsigned a2 = tf32(Ab[ra * ASTR + kh + t + 4]);
            unsigned a3 = tf32(Ab[(ra + 8) * ASTR + kh + t + 4]);
            const int kr = kt * 16 + kh;
#pragma unroll
            for (int j = 0; j < 4; j++) {
                unsigned b0 = Ws[(kr + t) * WSTR + noff + j * 8 + g];
                unsigned b1 = Ws[(kr + t + 4) * WSTR + noff + j * 8 + g];
                mma_tf32(acc[j][0], acc[j][1], acc[j][2], acc[j][3],
                         a0, a1, a2, a3, b0, b1);
            }
        }
        __syncthreads();
    }

    const int r0 = bm + ra;
    const int bb0 = r0 >> 11, ss0 = r0 & (SS - 1);
    const int r1 = r0 + 8;
    const int bb1 = r1 >> 11, ss1 = r1 & (SS - 1);
#pragma unroll
    for (int j = 0; j < 4; j++) {
#pragma unroll
        for (int u = 0; u < 2; u++) {
            int c = bn + noff + j * 8 + 2 * t + u;
            int hh = c & 7, hd = c >> 3;
            out[(((size_t)(bb0 * HH + hh) * SS) + ss0) * HDIM + hd] = acc[j][u];
            out[(((size_t)(bb1 * HH + hh) * SS) + ss1) * HDIM + hd] = acc[j][2 + u];
        }
    }
}

// ---------------- flash attention (both attentions, concat output) ------------
// grid (S/64, B*H, 2): z=0 self -> cols 0-127, z=1 cross -> cols 128-255
// of attn_cat (stride DCAT).  128 thr (4 warps), warp owns 16 query rows.
// exp split across pipes: 6 of 8 on MUFU, 2 on fma (exp2_poly) per iter.
#define VSTRIDE 136

__global__ void __launch_bounds__(128) attn_mma_kernel(
    const float* __restrict__ q1, const float* __restrict__ k1,
    const float* __restrict__ v1,
    const float* __restrict__ q2, const float* __restrict__ k2,
    const float* __restrict__ v2, float* __restrict__ ocat)
{
    const float* q = blockIdx.z ? q2 : q1;
    const float* k = blockIdx.z ? k2 : k1;
    const float* v = blockIdx.z ? v2 : v1;
    float* out = ocat + (blockIdx.z ? DD : 0);

    __shared__ unsigned Ks[128][8];
    __shared__ __nv_bfloat16 Vs[16][VSTRIDE];
    const int tid = threadIdx.x, w = tid >> 5, lane = tid & 31;
    const int bh = blockIdx.y, b = bh >> 3, h = bh & 7;
    const int g = lane >> 2, c = lane & 3;
    const size_t head = (size_t)bh * SS;
    const int qrow = blockIdx.x * 64 + w * 16;

    const float sc = 0.25f * 1.4426950408889634f;
    unsigned qa[4];
    {
        const float* r0 = q + (head + qrow + g) * HDIM;
        const float* r1 = r0 + 8 * HDIM;
        float2 t;
        t = *(const float2*)(r0 + 2 * c);     qa[0] = pack_bf16x2(t.x * sc, t.y * sc);
        t = *(const float2*)(r1 + 2 * c);     qa[1] = pack_bf16x2(t.x * sc, t.y * sc);
        t = *(const float2*)(r0 + 2 * c + 8); qa[2] = pack_bf16x2(t.x * sc, t.y * sc);
        t = *(const float2*)(r1 + 2 * c + 8); qa[3] = pack_bf16x2(t.x * sc, t.y * sc);
    }

    float o[8] = {0, 0, 0, 0, 0, 0, 0, 0};
    float l0 = 0.f, l1 = 0.f;

    for (int kt = 0; kt < SS / 128; kt++) {
        __syncthreads();
        const float4* ksrc = (const float4*)(k + (head + kt * 128) * HDIM);
        const float4* vsrc = (const float4*)(v + (head + kt * 128) * HDIM);
#pragma unroll
        for (int i = 0; i < 4; i++) {
            int idx = tid + i * 128;
            int key = idx >> 2, f4 = idx & 3;
            float4 t = ksrc[idx];
            Ks[key][f4 * 2]     = pack_bf16x2(t.x, t.y);
            Ks[key][f4 * 2 + 1] = pack_bf16x2(t.z, t.w);
            float4 u = vsrc[idx];
            Vs[f4 * 4 + 0][key] = __float2bfloat16(u.x);
            Vs[f4 * 4 + 1][key] = __float2bfloat16(u.y);
            Vs[f4 * 4 + 2][key] = __float2bfloat16(u.z);
            Vs[f4 * 4 + 3][key] = __float2bfloat16(u.w);
        }
        __syncthreads();

#pragma unroll
        for (int kc = 0; kc < 8; kc++) {
            float s0 = 0, s1 = 0, s2 = 0, s3 = 0, s4 = 0, s5 = 0, s6 = 0, s7 = 0;
            {
                unsigned b0 = Ks[kc * 16 + g][c];
                unsigned b1 = Ks[kc * 16 + g][c + 4];
                mma_bf16(s0, s1, s2, s3, qa[0], qa[1], qa[2], qa[3], b0, b1);
                b0 = Ks[kc * 16 + 8 + g][c];
                b1 = Ks[kc * 16 + 8 + g][c + 4];
                mma_bf16(s4, s5, s6, s7, qa[0], qa[1], qa[2], qa[3], b0, b1);
            }
            // 6 exps on MUFU, 2 on fma pipe (balances MUFU rt=8 vs fma headroom)
            float p0 = ex2(s0), p1 = exp2_poly(s1), p2 = ex2(s2), p3 = ex2(s3);
            float p4 = ex2(s4), p5 = exp2_poly(s5), p6 = ex2(s6), p7 = ex2(s7);
            l0 += (p0 + p1) + (p4 + p5);
            l1 += (p2 + p3) + (p6 + p7);
            unsigned A0 = pack_bf16x2(p0, p1);
            unsigned A1 = pack_bf16x2(p2, p3);
            unsigned A2 = pack_bf16x2(p4, p5);
            unsigned A3 = pack_bf16x2(p6, p7);
            unsigned vb0 = *(const unsigned*)&Vs[g][kc * 16 + 2 * c];
            unsigned vb1 = *(const unsigned*)&Vs[g][kc * 16 + 2 * c + 8];
            mma_bf16(o[0], o[1], o[2], o[3], A0, A1, A2, A3, vb0, vb1);
            vb0 = *(const unsigned*)&Vs[8 + g][kc * 16 + 2 * c];
            vb1 = *(const unsigned*)&Vs[8 + g][kc * 16 + 2 * c + 8];
            mma_bf16(o[4], o[5], o[6], o[7], A0, A1, A2, A3, vb0, vb1);
        }
    }

    l0 += __shfl_xor_sync(~0u, l0, 1); l0 += __shfl_xor_sync(~0u, l0, 2);
    l1 += __shfl_xor_sync(~0u, l1, 1); l1 += __shfl_xor_sync(~0u, l1, 2);
    const float inv0 = 1.0f / l0, inv1 = 1.0f / l1;

    // col = hd*8 + h (reference merge), row stride DCAT
    float* ob0 = out + ((size_t)(b * SS) + qrow + g) * DCAT + h;
    float* ob1 = out + ((size_t)(b * SS) + qrow + 8 + g) * DCAT + h;
    ob0[(2 * c) * HH]     = o[0] * inv0;
    ob0[(2 * c + 1) * HH] = o[1] * inv0;
    ob0[(8 + 2 * c) * HH] = o[4] * inv0;
    ob0[(9 + 2 * c) * HH] = o[5] * inv0;
    ob1[(2 * c) * HH]     = o[2] * inv1;
    ob1[(2 * c + 1) * HH] = o[3] * inv1;
    ob1[(8 + 2 * c) * HH] = o[6] * inv1;
    ob1[(9 + 2 * c) * HH] = o[7] * inv1;
}

// ---------------- LN row-stats: per row {mean, (D-1)/ss} ----------------------
// ln(x) = (x - mean) * (D-1)/ss, applied later in w3's fragment load.
__global__ void __launch_bounds__(256) stats_kernel(const float* __restrict__ x,
                                                    float2* __restrict__ st)
{
    int row  = blockIdx.x * 8 + (threadIdx.x >> 5);
    int lane = threadIdx.x & 31;
    float4 t = ((const float4*)(x + (size_t)row * DD))[lane];
    float s = t.x + t.y + t.z + t.w;
#pragma unroll
    for (int o = 16; o; o >>= 1) s += __shfl_xor_sync(~0u, s, o);
    float m = s * (1.0f / DD);
    float cx = t.x - m, cy = t.y - m, cz = t.z - m, cw = t.w - m;
    float ss = cx * cx + cy * cy + cz * cz + cw * cw;
#pragma unroll
    for (int o = 16; o; o >>= 1) ss += __shfl_xor_sync(~0u, ss, o);
    if (lane == 0) st[row] = make_float2(m, (float)(DD - 1) / ss);
}

// ---------------- launch --------------------------------------------------------
extern "C" void kernel_launch(void* const* d_in, const int* in_sizes, int n_in,
                              void* d_out, int out_size) {
    (void)in_sizes; (void)n_in; (void)out_size;
    const float* x_tgt = (const float*)d_in[0];
    const float* enc   = (const float*)d_in[1];
    const float* swq   = (const float*)d_in[2];
    const float* swk   = (const float*)d_in[3];
    const float* swv   = (const float*)d_in[4];
    const float* cwq   = (const float*)d_in[5];
    const float* cwk   = (const float*)d_in[6];
    const float* cwv   = (const float*)d_in[7];
    const float* w1    = (const float*)d_in[8];
    const float* b1    = (const float*)d_in[9];
    const float* w2    = (const float*)d_in[10];
    const float* b2    = (const float*)d_in[11];
    const float* w3    = (const float*)d_in[12];
    const float* b3    = (const float*)d_in[13];
    const float* w4    = (const float*)d_in[14];
    const float* b4    = (const float*)d_in[15];
    float* out = (float*)d_out;

    float *q1, *k1, *v1, *q2, *k2, *v2, *acat, *r2, *h;
    float2* st;
    cudaGetSymbolAddress((void**)&q1,   g_q1);
    cudaGetSymbolAddress((void**)&k1,   g_k1);
    cudaGetSymbolAddress((void**)&v1,   g_v1);
    cudaGetSymbolAddress((void**)&q2,   g_q2);
    cudaGetSymbolAddress((void**)&k2,   g_k2);
    cudaGetSymbolAddress((void**)&v2,   g_v2);
    cudaGetSymbolAddress((void**)&acat, g_attn_cat);
    cudaGetSymbolAddress((void**)&r2,   g_r2);
    cudaGetSymbolAddress((void**)&st,   g_stats);
    cudaGetSymbolAddress((void**)&h,    g_h);

    // dynamic smem: W panel + 2 A stages
    const int smQKV = DD * 72 * 4 + 2 * ATILE * 4;    // 47104
    const int smR2  = 256 * 40 * 4 + 2 * ATILE * 4;   // 51200 -> attribute
    const int smW3  = 128 * 72 * 4 + 2 * ATILE * 4;   // 47104
    const int smW4  = 512 * 40 * 4 + 2 * ATILE * 4;   // 92160 -> attribute
    cudaFuncSetAttribute(gemm_pipe_kernel<256, 128, 32, 3, 0>,
                         cudaFuncAttributeMaxDynamicSharedMemorySize, smR2);
    cudaFuncSetAttribute(gemm_pipe_kernel<512, 128, 32, 1, 0>,
                         cudaFuncAttributeMaxDynamicSharedMemorySize, smW4);

    const dim3 gQKV(12, MROWS / 64);              // all six projections
    const dim3 gA(SS / 64, BB * HH, 2);           // both attentions
    const dim3 gR2(4, MROWS / 64);                // fused r2 (K=256)
    const dim3 gW3(8, MROWS / 64);                // N=512, BN=64, LN-apply
    const dim3 gW4(4, MROWS / 64);                // K=512 -> N=128

    gemm_qkv6_kernel<<<gQKV, 256, smQKV>>>(x_tgt, enc, swq, swk, swv,
                                           cwq, cwk, cwv,
                                           q1, k1, v1, q2, k2, v2);
    attn_mma_kernel<<<gA, 128>>>(q1, k1, v1, q2, k2, v2, acat);
    // r2 = [attn1|attn2] @ [w1;w2] + b1 + b2 + x_tgt
    gemm_pipe_kernel<256, 128, 32, 3, 0><<<gR2, 256, smR2>>>(
        acat, w1, w2, b1, b2, x_tgt, nullptr, r2);
    stats_kernel<<<MROWS / 8, 256>>>(r2, st);
    // h = relu(ln(r2) @ w3 + b3), LN applied at fragment load
    gemm_pipe_kernel<128, 512, 64, 2, 1><<<gW3, 256, smW3>>>(
        r2, w3, nullptr, b3, nullptr, nullptr, st, h);
    gemm_pipe_kernel<512, 128, 32, 1, 0><<<gW4, 256, smW4>>>(
        h, w4, nullptr, b4, nullptr, r2, nullptr, out);
}

// round 9
// speedup vs baseline: 1.0348x; 1.0348x over previous
#include <cuda_runtime.h>
#include <cuda_bf16.h>

// Problem constants
#define BB 2
#define SS 2048
#define DD 128
#define HH 8
#define HDIM 16
#define DFF 512
#define MROWS (BB*SS)     // 4096
#define DCAT 256          // concat width of [attn1 | attn2]

// ---------------- scratch (device globals; no allocation allowed) -------------
__device__ float g_q1[BB*HH*SS*HDIM];
__device__ float g_k1[BB*HH*SS*HDIM];
__device__ float g_v1[BB*HH*SS*HDIM];
__device__ float g_q2[BB*HH*SS*HDIM];
__device__ float g_k2[BB*HH*SS*HDIM];
__device__ float g_v2[BB*HH*SS*HDIM];
__device__ float g_attn_cat[MROWS*DCAT];   // [row][0:128]=self, [128:256]=cross
__device__ float g_r2[BB*SS*DD];
__device__ float2 g_stats[MROWS];          // per-row {sum, sumsq} of r2
__device__ float g_h[BB*SS*DFF];

// ---------------- helpers -----------------------------------------------------
__device__ __forceinline__ unsigned pack_bf16x2(float lo, float hi) {
    unsigned r;
    asm("cvt.rn.bf16x2.f32 %0, %1, %2;" : "=r"(r) : "f"(hi), "f"(lo));
    return r;
}
__device__ __forceinline__ float ex2(float x) {
    float y;
    asm("ex2.approx.ftz.f32 %0, %1;" : "=f"(y) : "f"(x));
    return y;
}
__device__ __forceinline__ unsigned tf32(float x) {
    unsigned r;
    asm("cvt.rna.tf32.f32 %0, %1;" : "=r"(r) : "f"(x));
    return r;
}
__device__ __forceinline__ void mma_bf16(
    float& c0, float& c1, float& c2, float& c3,
    unsigned a0, unsigned a1, unsigned a2, unsigned a3,
    unsigned b0, unsigned b1)
{
    asm("mma.sync.aligned.m16n8k16.row.col.f32.bf16.bf16.f32 "
        "{%0,%1,%2,%3},{%4,%5,%6,%7},{%8,%9},{%0,%1,%2,%3};"
        : "+f"(c0), "+f"(c1), "+f"(c2), "+f"(c3)
        : "r"(a0), "r"(a1), "r"(a2), "r"(a3), "r"(b0), "r"(b1));
}
__device__ __forceinline__ void mma_tf32(
    float& c0, float& c1, float& c2, float& c3,
    unsigned a0, unsigned a1, unsigned a2, unsigned a3,
    unsigned b0, unsigned b1)
{
    asm("mma.sync.aligned.m16n8k8.row.col.f32.tf32.tf32.f32 "
        "{%0,%1,%2,%3},{%4,%5,%6,%7},{%8,%9},{%0,%1,%2,%3};"
        : "+f"(c0), "+f"(c1), "+f"(c2), "+f"(c3)
        : "r"(a0), "r"(a1), "r"(a2), "r"(a3), "r"(b0), "r"(b1));
}
__device__ __forceinline__ void cp16(unsigned dst, const void* src) {
    asm volatile("cp.async.cg.shared.global [%0], [%1], 16;"
                 :: "r"(dst), "l"(src));
}
__device__ __forceinline__ void cp_commit() {
    asm volatile("cp.async.commit_group;");
}
__device__ __forceinline__ void cp_wait1() {
    asm volatile("cp.async.wait_group 1;");
}

#define ASTR 20           // A-tile smem stride (words): 20g+t conflict-free
#define ATILE (64*ASTR)   // one A stage, words

// ---------------- cp.async-pipelined W-resident tf32 GEMM ---------------------
// out = A(MxK) @ W(KxN) + epilogue.  256 thr, 8 warps: 4 in M x 2 in N.
// W panel (K x BN) smem-resident (tf32, stride BN+8); A tiles (64x16 fp32)
// double-buffered via cp.async.
// EPI: 1 = +bias+res   2 = relu(+bias)
//      3 = fused r2 (W rows>=128 from W2, out = acc+bias+bias2+res) AND
//          accumulate per-row {sum, sumsq} of out into stats via atomicAdd
// LNA: A is pre-LN: a' = (a - m) * inv with m = sum/128, inv = 127/ss,
//      ss = sumsq - sum^2/128, read from stats (filled by the EPI==3 pass).
template<int K, int N, int BN, int EPI, int LNA>
__global__ void __launch_bounds__(256) gemm_pipe_kernel(
    const float* __restrict__ A, const float* __restrict__ W,
    const float* __restrict__ W2,
    const float* __restrict__ bias, const float* __restrict__ bias2,
    const float* __restrict__ res, float2* __restrict__ stats,
    float* __restrict__ out)
{
    constexpr int WSTR = BN + 8;
    constexpr int NT = BN / 16;          // n-tiles per warp
    constexpr int KT = K / 16;
    extern __shared__ unsigned smem[];
    unsigned* Ws = smem;                       // [K][WSTR] tf32
    float* As = (float*)(smem + K * WSTR);     // 2 x [64][ASTR] fp32
    const unsigned As_sh = (unsigned)__cvta_generic_to_shared(As);
    const int tid = threadIdx.x, warp = tid >> 5, lane = tid & 31;
    const int warp_m = warp >> 1, warp_n = warp & 1;
    const int g = lane >> 2, t = lane & 3;
    const int bm = blockIdx.y * 64, bn = blockIdx.x * BN;

    // stage whole weight panel (fp32 -> tf32), once
    for (int i = tid; i < K * (BN / 4); i += 256) {
        int row = i / (BN / 4), c = (i % (BN / 4)) * 4;
        float4 w4;
        if (EPI == 3 && row >= 128)
            w4 = *(const float4*)&W2[(size_t)(row - 128) * N + bn + c];
        else
            w4 = *(const float4*)&W[(size_t)row * N + bn + c];
        uint4 u = {tf32(w4.x), tf32(w4.y), tf32(w4.z), tf32(w4.w)};
        *(uint4*)&Ws[row * WSTR + c] = u;
    }

    // A prefetch: 64 rows x 16 k = 256 x 16B chunks, 1 per thread
    auto loadA = [&](int kt, int buf) {
        int row = tid >> 2, kc = (tid & 3) * 4;
        cp16(As_sh + (buf * ATILE + row * ASTR + kc) * 4,
             &A[(size_t)(bm + row) * K + kt * 16 + kc]);
        cp_commit();
    };
    loadA(0, 0);

    float acc[NT][4] = {};
    const int ra = warp_m * 16 + g;
    const int noff = warp_n * (BN / 2);

    float m0 = 0.f, i0 = 1.f, m1 = 0.f, i1 = 1.f;
    if (LNA) {
        float2 s0 = stats[bm + ra];
        float2 s1 = stats[bm + ra + 8];
        m0 = s0.x * (1.0f / DD);
        i0 = (float)(DD - 1) / (s0.y - s0.x * m0);
        m1 = s1.x * (1.0f / DD);
        i1 = (float)(DD - 1) / (s1.y - s1.x * m1);
    }

    for (int kt = 0; kt < KT; kt++) {
        if (kt + 1 < KT) loadA(kt + 1, (kt + 1) & 1);
        else cp_commit();                      // keep wait-group count aligned
        cp_wait1();
        __syncthreads();
        const float* Ab = As + (kt & 1) * ATILE;
#pragma unroll
        for (int kh = 0; kh < 16; kh += 8) {
            unsigned a0, a1, a2, a3;
            if (LNA) {
                a0 = tf32((Ab[ra * ASTR + kh + t] - m0) * i0);
                a1 = tf32((Ab[(ra + 8) * ASTR + kh + t] - m1) * i1);
                a2 = tf32((Ab[ra * ASTR + kh + t + 4] - m0) * i0);
                a3 = tf32((Ab[(ra + 8) * ASTR + kh + t + 4] - m1) * i1);
            } else {
                a0 = tf32(Ab[ra * ASTR + kh + t]);
                a1 = tf32(Ab[(ra + 8) * ASTR + kh + t]);
                a2 = tf32(Ab[ra * ASTR + kh + t + 4]);
                a3 = tf32(Ab[(ra + 8) * ASTR + kh + t + 4]);
            }
            const int kr = kt * 16 + kh;
#pragma unroll
            for (int j = 0; j < NT; j++) {
                unsigned b0 = Ws[(kr + t) * WSTR + noff + j * 8 + g];
                unsigned b1 = Ws[(kr + t + 4) * WSTR + noff + j * 8 + g];
                mma_tf32(acc[j][0], acc[j][1], acc[j][2], acc[j][3],
                         a0, a1, a2, a3, b0, b1);
            }
        }
        __syncthreads();
    }

    const int r0 = bm + ra;
    float s0 = 0.f, q0 = 0.f, s1 = 0.f, q1 = 0.f;   // stats partials (EPI==3)
#pragma unroll
    for (int j = 0; j < NT; j++) {
        int c0 = bn + noff + j * 8 + 2 * t;
        if (EPI == 1 || EPI == 3) {
            float2 bi = *(const float2*)&bias[c0];
            if (EPI == 3) {
                float2 bi2 = *(const float2*)&bias2[c0];
                bi.x += bi2.x; bi.y += bi2.y;
            }
            float2 rA = *(const float2*)&res[(size_t)r0 * N + c0];
            float2 rB = *(const float2*)&res[(size_t)(r0 + 8) * N + c0];
            float2 oA = {acc[j][0] + bi.x + rA.x, acc[j][1] + bi.y + rA.y};
            float2 oB = {acc[j][2] + bi.x + rB.x, acc[j][3] + bi.y + rB.y};
            *(float2*)&out[(size_t)r0 * N + c0] = oA;
            *(float2*)&out[(size_t)(r0 + 8) * N + c0] = oB;
            if (EPI == 3) {
                s0 += oA.x + oA.y; q0 += oA.x * oA.x + oA.y * oA.y;
                s1 += oB.x + oB.y; q1 += oB.x * oB.x + oB.y * oB.y;
            }
        } else {
            float2 bi = *(const float2*)&bias[c0];
            float2 oA = {fmaxf(acc[j][0] + bi.x, 0.f), fmaxf(acc[j][1] + bi.y, 0.f)};
            float2 oB = {fmaxf(acc[j][2] + bi.x, 0.f), fmaxf(acc[j][3] + bi.y, 0.f)};
            *(float2*)&out[(size_t)r0 * N + c0] = oA;
            *(float2*)&out[(size_t)(r0 + 8) * N + c0] = oB;
        }
    }
    if (EPI == 3) {
        // quad-reduce over t (lanes 4g..4g+3), one atomic pair per (row, warp)
        s0 += __shfl_xor_sync(~0u, s0, 1); s0 += __shfl_xor_sync(~0u, s0, 2);
        q0 += __shfl_xor_sync(~0u, q0, 1); q0 += __shfl_xor_sync(~0u, q0, 2);
        s1 += __shfl_xor_sync(~0u, s1, 1); s1 += __shfl_xor_sync(~0u, s1, 2);
        q1 += __shfl_xor_sync(~0u, q1, 1); q1 += __shfl_xor_sync(~0u, q1, 2);
        if (t == 0) {
            atomicAdd(&stats[r0].x, s0);
            atomicAdd(&stats[r0].y, q0);
            atomicAdd(&stats[r0 + 8].x, s1);
            atomicAdd(&stats[r0 + 8].y, q1);
        }
    }
}

// ---------------- ALL-SIX QKV projections in one launch (pipelined) -----------
// grid (12, 64), 256 thr/8 warps: blockIdx.x>>1 = {sq, sk, sv, cq, ck, cv}
// (cross Q reads enc_out — the reference's quirk).  Scatter col c ->
// h=c&7, hd=c>>3 into [b][h][s][hd].  Also zeroes the LN-stats buffer
// (3 launches upstream of its first atomicAdd — ordering by kernel boundary).
__global__ void __launch_bounds__(256) gemm_qkv6_kernel(
    const float* __restrict__ x_tgt, const float* __restrict__ enc,
    const float* __restrict__ swq, const float* __restrict__ swk,
    const float* __restrict__ swv, const float* __restrict__ cwq,
    const float* __restrict__ cwk, const float* __restrict__ cwv,
    float* __restrict__ q1, float* __restrict__ k1, float* __restrict__ v1,
    float* __restrict__ q2, float* __restrict__ k2, float* __restrict__ v2,
    float2* __restrict__ stats)
{
    const int which = blockIdx.x >> 1;
    const float* A = (which == 3) ? enc : x_tgt;
    const float* W; float* out;
    switch (which) {
        case 0: W = swq; out = q1; break;
        case 1: W = swk; out = k1; break;
        case 2: W = swv; out = v1; break;
        case 3: W = cwq; out = q2; break;
        case 4: W = cwk; out = k2; break;
        default: W = cwv; out = v2; break;
    }

    // zero LN-stats: blocks in column 0 each clear their 64 rows
    if (blockIdx.x == 0 && threadIdx.x < 128) {
        ((float*)&stats[blockIdx.y * 64])[threadIdx.x] = 0.f;
    }

    constexpr int WSTR = 72;
    extern __shared__ unsigned smem[];
    unsigned* Ws = smem;                       // [128][72]
    float* As = (float*)(smem + DD * WSTR);
    const unsigned As_sh = (unsigned)__cvta_generic_to_shared(As);
    const int tid = threadIdx.x, warp = tid >> 5, lane = tid & 31;
    const int warp_m = warp >> 1, warp_n = warp & 1;
    const int g = lane >> 2, t = lane & 3;
    const int bm = blockIdx.y * 64, bn = (blockIdx.x & 1) * 64;

    for (int i = tid; i < DD * 16; i += 256) {
        int row = i / 16, c = (i % 16) * 4;
        float4 w4 = *(const float4*)&W[(size_t)row * DD + bn + c];
        uint4 u = {tf32(w4.x), tf32(w4.y), tf32(w4.z), tf32(w4.w)};
        *(uint4*)&Ws[row * WSTR + c] = u;
    }

    auto loadA = [&](int kt, int buf) {
        int row = tid >> 2, kc = (tid & 3) * 4;
        cp16(As_sh + (buf * ATILE + row * ASTR + kc) * 4,
             &A[(size_t)(bm + row) * DD + kt * 16 + kc]);
        cp_commit();
    };
    loadA(0, 0);

    float acc[4][4] = {};
    const int ra = warp_m * 16 + g;
    const int noff = warp_n * 32;

    for (int kt = 0; kt < DD / 16; kt++) {
        if (kt + 1 < DD / 16) loadA(kt + 1, (kt + 1) & 1);
        else cp_commit();
        cp_wait1();
        __syncthreads();
        const float* Ab = As + (kt & 1) * ATILE;
#pragma unroll
        for (int kh = 0; kh < 16; kh += 8) {
            unsigned a0 = tf32(Ab[ra * ASTR + kh + t]);
            unsigned a1 = tf32(Ab[(ra + 8) * ASTR + kh + t]);
            unsigned a2 = tf32(Ab[ra * ASTR + kh + t + 4]);
            unsigned a3 = tf32(Ab[(ra + 8) * ASTR + kh + t + 4]);
            const int kr = kt * 16 + kh;
#pragma unroll
            for (int j = 0; j < 4; j++) {
                unsigned b0 = Ws[(kr + t) * WSTR + noff + j * 8 + g];
                unsigned b1 = Ws[(kr + t + 4) * WSTR + noff + j * 8 + g];
                mma_tf32(acc[j][0], acc[j][1], acc[j][2], acc[j][3],
                         a0, a1, a2, a3, b0, b1);
            }
        }
        __syncthreads();
    }

    const int r0 = bm + ra;
    const int bb0 = r0 >> 11, ss0 = r0 & (SS - 1);
    const int r1 = r0 + 8;
    const int bb1 = r1 >> 11, ss1 = r1 & (SS - 1);
#pragma unroll
    for (int j = 0; j < 4; j++) {
#pragma unroll
        for (int u = 0; u < 2; u++) {
            int c = bn + noff + j * 8 + 2 * t + u;
            int hh = c & 7, hd = c >> 3;
            out[(((size_t)(bb0 * HH + hh) * SS) + ss0) * HDIM + hd] = acc[j][u];
            out[(((size_t)(bb1 * HH + hh) * SS) + ss1) * HDIM + hd] = acc[j][2 + u];
        }
    }
}

// ---------------- flash attention (both attentions, concat output) ------------
// grid (S/64, B*H, 2): z=0 self -> cols 0-127, z=1 cross -> cols 128-255
// of attn_cat (stride DCAT).  128 thr (4 warps), warp owns 16 query rows.
#define VSTRIDE 136

__global__ void __launch_bounds__(128) attn_mma_kernel(
    const float* __restrict__ q1, const float* __restrict__ k1,
    const float* __restrict__ v1,
    const float* __restrict__ q2, const float* __restrict__ k2,
    const float* __restrict__ v2, float* __restrict__ ocat)
{
    const float* q = blockIdx.z ? q2 : q1;
    const float* k = blockIdx.z ? k2 : k1;
    const float* v = blockIdx.z ? v2 : v1;
    float* out = ocat + (blockIdx.z ? DD : 0);

    __shared__ unsigned Ks[128][8];
    __shared__ __nv_bfloat16 Vs[16][VSTRIDE];
    const int tid = threadIdx.x, w = tid >> 5, lane = tid & 31;
    const int bh = blockIdx.y, b = bh >> 3, h = bh & 7;
    const int g = lane >> 2, c = lane & 3;
    const size_t head = (size_t)bh * SS;
    const int qrow = blockIdx.x * 64 + w * 16;

    const float sc = 0.25f * 1.4426950408889634f;
    unsigned qa[4];
    {
        const float* r0 = q + (head + qrow + g) * HDIM;
        const float* r1 = r0 + 8 * HDIM;
        float2 t;
        t = *(const float2*)(r0 + 2 * c);     qa[0] = pack_bf16x2(t.x * sc, t.y * sc);
        t = *(const float2*)(r1 + 2 * c);     qa[1] = pack_bf16x2(t.x * sc, t.y * sc);
        t = *(const float2*)(r0 + 2 * c + 8); qa[2] = pack_bf16x2(t.x * sc, t.y * sc);
        t = *(const float2*)(r1 + 2 * c + 8); qa[3] = pack_bf16x2(t.x * sc, t.y * sc);
    }

    float o[8] = {0, 0, 0, 0, 0, 0, 0, 0};
    float l0 = 0.f, l1 = 0.f;

    for (int kt = 0; kt < SS / 128; kt++) {
        __syncthreads();
        const float4* ksrc = (const float4*)(k + (head + kt * 128) * HDIM);
        const float4* vsrc = (const float4*)(v + (head + kt * 128) * HDIM);
#pragma unroll
        for (int i = 0; i < 4; i++) {
            int idx = tid + i * 128;
            int key = idx >> 2, f4 = idx & 3;
            float4 t = ksrc[idx];
            Ks[key][f4 * 2]     = pack_bf16x2(t.x, t.y);
            Ks[key][f4 * 2 + 1] = pack_bf16x2(t.z, t.w);
            float4 u = vsrc[idx];
            Vs[f4 * 4 + 0][key] = __float2bfloat16(u.x);
            Vs[f4 * 4 + 1][key] = __float2bfloat16(u.y);
            Vs[f4 * 4 + 2][key] = __float2bfloat16(u.z);
            Vs[f4 * 4 + 3][key] = __float2bfloat16(u.w);
        }
        __syncthreads();

#pragma unroll
        for (int kc = 0; kc < 8; kc++) {
            float s0 = 0, s1 = 0, s2 = 0, s3 = 0, s4 = 0, s5 = 0, s6 = 0, s7 = 0;
            {
                unsigned b0 = Ks[kc * 16 + g][c];
                unsigned b1 = Ks[kc * 16 + g][c + 4];
                mma_bf16(s0, s1, s2, s3, qa[0], qa[1], qa[2], qa[3], b0, b1);
                b0 = Ks[kc * 16 + 8 + g][c];
                b1 = Ks[kc * 16 + 8 + g][c + 4];
                mma_bf16(s4, s5, s6, s7, qa[0], qa[1], qa[2], qa[3], b0, b1);
            }
            float p0 = ex2(s0), p1 = ex2(s1), p2 = ex2(s2), p3 = ex2(s3);
            float p4 = ex2(s4), p5 = ex2(s5), p6 = ex2(s6), p7 = ex2(s7);
            l0 += (p0 + p1) + (p4 + p5);
            l1 += (p2 + p3) + (p6 + p7);
            unsigned A0 = pack_bf16x2(p0, p1);
            unsigned A1 = pack_bf16x2(p2, p3);
            unsigned A2 = pack_bf16x2(p4, p5);
            unsigned A3 = pack_bf16x2(p6, p7);
            unsigned vb0 = *(const unsigned*)&Vs[g][kc * 16 + 2 * c];
            unsigned vb1 = *(const unsigned*)&Vs[g][kc * 16 + 2 * c + 8];
            mma_bf16(o[0], o[1], o[2], o[3], A0, A1, A2, A3, vb0, vb1);
            vb0 = *(const unsigned*)&Vs[8 + g][kc * 16 + 2 * c];
            vb1 = *(const unsigned*)&Vs[8 + g][kc * 16 + 2 * c + 8];
            mma_bf16(o[4], o[5], o[6], o[7], A0, A1, A2, A3, vb0, vb1);
        }
    }

    l0 += __shfl_xor_sync(~0u, l0, 1); l0 += __shfl_xor_sync(~0u, l0, 2);
    l1 += __shfl_xor_sync(~0u, l1, 1); l1 += __shfl_xor_sync(~0u, l1, 2);
    const float inv0 = 1.0f / l0, inv1 = 1.0f / l1;

    // col = hd*8 + h (reference merge), row stride DCAT
    float* ob0 = out + ((size_t)(b * SS) + qrow + g) * DCAT + h;
    float* ob1 = out + ((size_t)(b * SS) + qrow + 8 + g) * DCAT + h;
    ob0[(2 * c) * HH]     = o[0] * inv0;
    ob0[(2 * c + 1) * HH] = o[1] * inv0;
    ob0[(8 + 2 * c) * HH] = o[4] * inv0;
    ob0[(9 + 2 * c) * HH] = o[5] * inv0;
    ob1[(2 * c) * HH]     = o[2] * inv1;
    ob1[(2 * c + 1) * HH] = o[3] * inv1;
    ob1[(8 + 2 * c) * HH] = o[6] * inv1;
    ob1[(9 + 2 * c) * HH] = o[7] * inv1;
}

// ---------------- launch --------------------------------------------------------
extern "C" void kernel_launch(void* const* d_in, const int* in_sizes, int n_in,
                              void* d_out, int out_size) {
    (void)in_sizes; (void)n_in; (void)out_size;
    const float* x_tgt = (const float*)d_in[0];
    const float* enc   = (const float*)d_in[1];
    const float* swq   = (const float*)d_in[2];
    const float* swk   = (const float*)d_in[3];
    const float* swv   = (const float*)d_in[4];
    const float* cwq   = (const float*)d_in[5];
    const float* cwk   = (const float*)d_in[6];
    const float* cwv   = (const float*)d_in[7];
    const float* w1    = (const float*)d_in[8];
    const float* b1    = (const float*)d_in[9];
    const float* w2    = (const float*)d_in[10];
    const float* b2    = (const float*)d_in[11];
    const float* w3    = (const float*)d_in[12];
    const float* b3    = (const float*)d_in[13];
    const float* w4    = (const float*)d_in[14];
    const float* b4    = (const float*)d_in[15];
    float* out = (float*)d_out;

    float *q1, *k1, *v1, *q2, *k2, *v2, *acat, *r2, *h;
    float2* st;
    cudaGetSymbolAddress((void**)&q1,   g_q1);
    cudaGetSymbolAddress((void**)&k1,   g_k1);
    cudaGetSymbolAddress((void**)&v1,   g_v1);
    cudaGetSymbolAddress((void**)&q2,   g_q2);
    cudaGetSymbolAddress((void**)&k2,   g_k2);
    cudaGetSymbolAddress((void**)&v2,   g_v2);
    cudaGetSymbolAddress((void**)&acat, g_attn_cat);
    cudaGetSymbolAddress((void**)&r2,   g_r2);
    cudaGetSymbolAddress((void**)&st,   g_stats);
    cudaGetSymbolAddress((void**)&h,    g_h);

    // dynamic smem: W panel + 2 A stages
    const int smQKV = DD * 72 * 4 + 2 * ATILE * 4;    // 47104
    const int smR2  = 256 * 40 * 4 + 2 * ATILE * 4;   // 51200 -> attribute
    const int smW3  = 128 * 72 * 4 + 2 * ATILE * 4;   // 47104
    const int smW4  = 512 * 40 * 4 + 2 * ATILE * 4;   // 92160 -> attribute
    cudaFuncSetAttribute(gemm_pipe_kernel<256, 128, 32, 3, 0>,
                         cudaFuncAttributeMaxDynamicSharedMemorySize, smR2);
    cudaFuncSetAttribute(gemm_pipe_kernel<512, 128, 32, 1, 0>,
                         cudaFuncAttributeMaxDynamicSharedMemorySize, smW4);

    const dim3 gQKV(12, MROWS / 64);              // all six projections
    const dim3 gA(SS / 64, BB * HH, 2);           // both attentions
    const dim3 gR2(4, MROWS / 64);                // fused r2 (K=256) + stats
    const dim3 gW3(8, MROWS / 64);                // N=512, BN=64, LN-apply
    const dim3 gW4(4, MROWS / 64);                // K=512 -> N=128

    gemm_qkv6_kernel<<<gQKV, 256, smQKV>>>(x_tgt, enc, swq, swk, swv,
                                           cwq, cwk, cwv,
                                           q1, k1, v1, q2, k2, v2, st);
    attn_mma_kernel<<<gA, 128>>>(q1, k1, v1, q2, k2, v2, acat);
    // r2 = [attn1|attn2] @ [w1;w2] + b1 + b2 + x_tgt; also emits LN stats
    gemm_pipe_kernel<256, 128, 32, 3, 0><<<gR2, 256, smR2>>>(
        acat, w1, w2, b1, b2, x_tgt, st, r2);
    // h = relu(ln(r2) @ w3 + b3), LN applied at fragment load from stats
    gemm_pipe_kernel<128, 512, 64, 2, 1><<<gW3, 256, smW3>>>(
        r2, w3, nullptr, b3, nullptr, nullptr, st, h);
    gemm_pipe_kernel<512, 128, 32, 1, 0><<<gW4, 256, smW4>>>(
        h, w4, nullptr, b4, nullptr, r2, nullptr, out);
}

// round 10
// speedup vs baseline: 1.0769x; 1.0407x over previous
#include <cuda_runtime.h>
#include <cuda_bf16.h>

// Problem constants
#define BB 2
#define SS 2048
#define DD 128
#define HH 8
#define HDIM 16
#define DFF 512
#define MROWS (BB*SS)     // 4096
#define DCAT 256          // concat width of [attn1 | attn2]

// ---------------- scratch (device globals; no allocation allowed) -------------
__device__ float g_q1[BB*HH*SS*HDIM];
__device__ float g_k1[BB*HH*SS*HDIM];
__device__ float g_v1[BB*HH*SS*HDIM];
__device__ float g_q2[BB*HH*SS*HDIM];
__device__ float g_k2[BB*HH*SS*HDIM];
__device__ float g_v2[BB*HH*SS*HDIM];
__device__ float g_attn_cat[MROWS*DCAT];   // [row][0:128]=self, [128:256]=cross
__device__ float g_r2[BB*SS*DD];
__device__ float2 g_stats[MROWS];          // per-row {sum, sumsq} of r2
__device__ float g_h[BB*SS*DFF];

// ---------------- helpers -----------------------------------------------------
__device__ __forceinline__ unsigned pack_bf16x2(float lo, float hi) {
    unsigned r;
    asm("cvt.rn.bf16x2.f32 %0, %1, %2;" : "=r"(r) : "f"(hi), "f"(lo));
    return r;
}
__device__ __forceinline__ float ex2(float x) {
    float y;
    asm("ex2.approx.ftz.f32 %0, %1;" : "=f"(y) : "f"(x));
    return y;
}
__device__ __forceinline__ unsigned tf32(float x) {
    unsigned r;
    asm("cvt.rna.tf32.f32 %0, %1;" : "=r"(r) : "f"(x));
    return r;
}
__device__ __forceinline__ void mma_bf16(
    float& c0, float& c1, float& c2, float& c3,
    unsigned a0, unsigned a1, unsigned a2, unsigned a3,
    unsigned b0, unsigned b1)
{
    asm("mma.sync.aligned.m16n8k16.row.col.f32.bf16.bf16.f32 "
        "{%0,%1,%2,%3},{%4,%5,%6,%7},{%8,%9},{%0,%1,%2,%3};"
        : "+f"(c0), "+f"(c1), "+f"(c2), "+f"(c3)
        : "r"(a0), "r"(a1), "r"(a2), "r"(a3), "r"(b0), "r"(b1));
}
__device__ __forceinline__ void mma_tf32(
    float& c0, float& c1, float& c2, float& c3,
    unsigned a0, unsigned a1, unsigned a2, unsigned a3,
    unsigned b0, unsigned b1)
{
    asm("mma.sync.aligned.m16n8k8.row.col.f32.tf32.tf32.f32 "
        "{%0,%1,%2,%3},{%4,%5,%6,%7},{%8,%9},{%0,%1,%2,%3};"
        : "+f"(c0), "+f"(c1), "+f"(c2), "+f"(c3)
        : "r"(a0), "r"(a1), "r"(a2), "r"(a3), "r"(b0), "r"(b1));
}
__device__ __forceinline__ void cp16(unsigned dst, const void* src) {
    asm volatile("cp.async.cg.shared.global [%0], [%1], 16;"
                 :: "r"(dst), "l"(src));
}
__device__ __forceinline__ void cp_commit() {
    asm volatile("cp.async.commit_group;");
}
__device__ __forceinline__ void cp_wait1() {
    asm volatile("cp.async.wait_group 1;");
}

#define ASTR 20           // A-tile smem stride (words)
#define ATILE (64*ASTR)   // one A stage, words

// ---------------- tf32 pipelined GEMM — r2 ONLY (precision-critical) ----------
// r2 = [attn1|attn2](Mx256) @ [w1;w2] + b1 + b2 + x_tgt, and accumulates
// per-row {sum, sumsq} of the output into stats via atomicAdd.
template<int K, int N, int BN>
__global__ void __launch_bounds__(256) gemm_r2_kernel(
    const float* __restrict__ A, const float* __restrict__ W,
    const float* __restrict__ W2,
    const float* __restrict__ bias, const float* __restrict__ bias2,
    const float* __restrict__ res, float2* __restrict__ stats,
    float* __restrict__ out)
{
    constexpr int WSTR = BN + 8;
    constexpr int NT = BN / 16;
    constexpr int KT = K / 16;
    extern __shared__ unsigned smem[];
    unsigned* Ws = smem;                       // [K][WSTR] tf32
    float* As = (float*)(smem + K * WSTR);     // 2 x [64][ASTR] fp32
    const unsigned As_sh = (unsigned)__cvta_generic_to_shared(As);
    const int tid = threadIdx.x, warp = tid >> 5, lane = tid & 31;
    const int warp_m = warp >> 1, warp_n = warp & 1;
    const int g = lane >> 2, t = lane & 3;
    const int bm = blockIdx.y * 64, bn = blockIdx.x * BN;

    for (int i = tid; i < K * (BN / 4); i += 256) {
        int row = i / (BN / 4), c = (i % (BN / 4)) * 4;
        float4 w4;
        if (row >= 128)
            w4 = *(const float4*)&W2[(size_t)(row - 128) * N + bn + c];
        else
            w4 = *(const float4*)&W[(size_t)row * N + bn + c];
        uint4 u = {tf32(w4.x), tf32(w4.y), tf32(w4.z), tf32(w4.w)};
        *(uint4*)&Ws[row * WSTR + c] = u;
    }

    auto loadA = [&](int kt, int buf) {
        int row = tid >> 2, kc = (tid & 3) * 4;
        cp16(As_sh + (buf * ATILE + row * ASTR + kc) * 4,
             &A[(size_t)(bm + row) * K + kt * 16 + kc]);
        cp_commit();
    };
    loadA(0, 0);

    float acc[NT][4] = {};
    const int ra = warp_m * 16 + g;
    const int noff = warp_n * (BN / 2);

    for (int kt = 0; kt < KT; kt++) {
        if (kt + 1 < KT) loadA(kt + 1, (kt + 1) & 1);
        else cp_commit();
        cp_wait1();
        __syncthreads();
        const float* Ab = As + (kt & 1) * ATILE;
#pragma unroll
        for (int kh = 0; kh < 16; kh += 8) {
            unsigned a0 = tf32(Ab[ra * ASTR + kh + t]);
            unsigned a1 = tf32(Ab[(ra + 8) * ASTR + kh + t]);
            unsigned a2 = tf32(Ab[ra * ASTR + kh + t + 4]);
            unsigned a3 = tf32(Ab[(ra + 8) * ASTR + kh + t + 4]);
            const int kr = kt * 16 + kh;
#pragma unroll
            for (int j = 0; j < NT; j++) {
                unsigned b0 = Ws[(kr + t) * WSTR + noff + j * 8 + g];
                unsigned b1 = Ws[(kr + t + 4) * WSTR + noff + j * 8 + g];
                mma_tf32(acc[j][0], acc[j][1], acc[j][2], acc[j][3],
                         a0, a1, a2, a3, b0, b1);
            }
        }
        __syncthreads();
    }

    const int r0 = bm + ra;
    float s0 = 0.f, q0 = 0.f, s1 = 0.f, q1 = 0.f;
#pragma unroll
    for (int j = 0; j < NT; j++) {
        int c0 = bn + noff + j * 8 + 2 * t;
        float2 bi = *(const float2*)&bias[c0];
        float2 bi2 = *(const float2*)&bias2[c0];
        bi.x += bi2.x; bi.y += bi2.y;
        float2 rA = *(const float2*)&res[(size_t)r0 * N + c0];
        float2 rB = *(const float2*)&res[(size_t)(r0 + 8) * N + c0];
        float2 oA = {acc[j][0] + bi.x + rA.x, acc[j][1] + bi.y + rA.y};
        float2 oB = {acc[j][2] + bi.x + rB.x, acc[j][3] + bi.y + rB.y};
        *(float2*)&out[(size_t)r0 * N + c0] = oA;
        *(float2*)&out[(size_t)(r0 + 8) * N + c0] = oB;
        s0 += oA.x + oA.y; q0 += oA.x * oA.x + oA.y * oA.y;
        s1 += oB.x + oB.y; q1 += oB.x * oB.x + oB.y * oB.y;
    }
    s0 += __shfl_xor_sync(~0u, s0, 1); s0 += __shfl_xor_sync(~0u, s0, 2);
    q0 += __shfl_xor_sync(~0u, q0, 1); q0 += __shfl_xor_sync(~0u, q0, 2);
    s1 += __shfl_xor_sync(~0u, s1, 1); s1 += __shfl_xor_sync(~0u, s1, 2);
    q1 += __shfl_xor_sync(~0u, q1, 1); q1 += __shfl_xor_sync(~0u, q1, 2);
    if (t == 0) {
        atomicAdd(&stats[r0].x, s0);
        atomicAdd(&stats[r0].y, q0);
        atomicAdd(&stats[r0 + 8].x, s1);
        atomicAdd(&stats[r0 + 8].y, q1);
    }
}

// ---------------- bf16 pipelined GEMM (m16n8k16) — w3 / w4 --------------------
// W packed bf16x2 along k into smem ([K/2][BN+8] words); A tiles (fp32)
// double-buffered via cp.async, packed to bf16x2 at fragment load.
// Per k16 per warp: 4 LDS.64 + 4 pack + NT x (2 LDS + 1 mma) — ~half the
// issue stream of the tf32 m16n8k8 version.
// EPI: 1 = +bias+res   2 = relu(+bias)
// LNA: a' = (a - m) * inv from stats {sum, sumsq}: m=sum/128, inv=127/ss.
template<int K, int N, int BN, int EPI, int LNA>
__global__ void __launch_bounds__(256) gemm_bf16_kernel(
    const float* __restrict__ A, const float* __restrict__ W,
    const float* __restrict__ bias, const float* __restrict__ res,
    const float2* __restrict__ stats, float* __restrict__ out)
{
    constexpr int WSTR = BN + 8;
    constexpr int NT = BN / 16;
    constexpr int KT = K / 16;
    extern __shared__ unsigned smem[];
    unsigned* Ws = smem;                       // [K/2][WSTR] bf16x2 (k-pairs)
    float* As = (float*)(smem + (K / 2) * WSTR);
    const unsigned As_sh = (unsigned)__cvta_generic_to_shared(As);
    const int tid = threadIdx.x, warp = tid >> 5, lane = tid & 31;
    const int warp_m = warp >> 1, warp_n = warp & 1;
    const int g = lane >> 2, t = lane & 3;
    const int bm = blockIdx.y * 64, bn = blockIdx.x * BN;

    // stage W packed along k: Ws[p][n] = {W[2p][n], W[2p+1][n]}
    for (int i = tid; i < (K / 2) * (BN / 4); i += 256) {
        int p = i / (BN / 4), c = (i % (BN / 4)) * 4;
        float4 wa = *(const float4*)&W[(size_t)(2 * p) * N + bn + c];
        float4 wb = *(const float4*)&W[(size_t)(2 * p + 1) * N + bn + c];
        uint4 u = {pack_bf16x2(wa.x, wb.x), pack_bf16x2(wa.y, wb.y),
                   pack_bf16x2(wa.z, wb.z), pack_bf16x2(wa.w, wb.w)};
        *(uint4*)&Ws[p * WSTR + c] = u;
    }

    auto loadA = [&](int kt, int buf) {
        int row = tid >> 2, kc = (tid & 3) * 4;
        cp16(As_sh + (buf * ATILE + row * ASTR + kc) * 4,
             &A[(size_t)(bm + row) * K + kt * 16 + kc]);
        cp_commit();
    };
    loadA(0, 0);

    float acc[NT][4] = {};
    const int ra = warp_m * 16 + g;
    const int noff = warp_n * (BN / 2);

    float m0 = 0.f, i0 = 1.f, m1 = 0.f, i1 = 1.f;
    if (LNA) {
        float2 st0 = stats[bm + ra];
        float2 st1 = stats[bm + ra + 8];
        m0 = st0.x * (1.0f / DD);
        i0 = (float)(DD - 1) / (st0.y - st0.x * m0);
        m1 = st1.x * (1.0f / DD);
        i1 = (float)(DD - 1) / (st1.y - st1.x * m1);
    }
    const float mi0 = -m0 * i0, mi1 = -m1 * i1;

    for (int kt = 0; kt < KT; kt++) {
        if (kt + 1 < KT) loadA(kt + 1, (kt + 1) & 1);
        else cp_commit();
        cp_wait1();
        __syncthreads();
        const float* Ab = As + (kt & 1) * ATILE;
        float2 x0 = *(const float2*)&Ab[ra * ASTR + 2 * t];
        float2 x1 = *(const float2*)&Ab[(ra + 8) * ASTR + 2 * t];
        float2 x2 = *(const float2*)&Ab[ra * ASTR + 2 * t + 8];
        float2 x3 = *(const float2*)&Ab[(ra + 8) * ASTR + 2 * t + 8];
        if (LNA) {
            x0.x = fmaf(x0.x, i0, mi0); x0.y = fmaf(x0.y, i0, mi0);
            x1.x = fmaf(x1.x, i1, mi1); x1.y = fmaf(x1.y, i1, mi1);
            x2.x = fmaf(x2.x, i0, mi0); x2.y = fmaf(x2.y, i0, mi0);
            x3.x = fmaf(x3.x, i1, mi1); x3.y = fmaf(x3.y, i1, mi1);
        }
        unsigned a0 = pack_bf16x2(x0.x, x0.y);
        unsigned a1 = pack_bf16x2(x1.x, x1.y);
        unsigned a2 = pack_bf16x2(x2.x, x2.y);
        unsigned a3 = pack_bf16x2(x3.x, x3.y);
        const int kp = kt * 8;
#pragma unroll
        for (int j = 0; j < NT; j++) {
            unsigned b0 = Ws[(kp + t) * WSTR + noff + j * 8 + g];
            unsigned b1 = Ws[(kp + t + 4) * WSTR + noff + j * 8 + g];
            mma_bf16(acc[j][0], acc[j][1], acc[j][2], acc[j][3],
                     a0, a1, a2, a3, b0, b1);
        }
        __syncthreads();
    }

    const int r0 = bm + ra;
#pragma unroll
    for (int j = 0; j < NT; j++) {
        int c0 = bn + noff + j * 8 + 2 * t;
        float2 bi = *(const float2*)&bias[c0];
        if (EPI == 1) {
            float2 rA = *(const float2*)&res[(size_t)r0 * N + c0];
            float2 rB = *(const float2*)&res[(size_t)(r0 + 8) * N + c0];
            float2 oA = {acc[j][0] + bi.x + rA.x, acc[j][1] + bi.y + rA.y};
            float2 oB = {acc[j][2] + bi.x + rB.x, acc[j][3] + bi.y + rB.y};
            *(float2*)&out[(size_t)r0 * N + c0] = oA;
            *(float2*)&out[(size_t)(r0 + 8) * N + c0] = oB;
        } else {
            float2 oA = {fmaxf(acc[j][0] + bi.x, 0.f), fmaxf(acc[j][1] + bi.y, 0.f)};
            float2 oB = {fmaxf(acc[j][2] + bi.x, 0.f), fmaxf(acc[j][3] + bi.y, 0.f)};
            *(float2*)&out[(size_t)r0 * N + c0] = oA;
            *(float2*)&out[(size_t)(r0 + 8) * N + c0] = oB;
        }
    }
}

// ---------------- ALL-SIX QKV projections, bf16 mma (scatter epilogue) --------
// grid (12, 64), 256 thr/8 warps: blockIdx.x>>1 = {sq, sk, sv, cq, ck, cv}
// (cross Q reads enc_out — the reference's quirk).  Scatter col c ->
// h=c&7, hd=c>>3 into [b][h][s][hd].  Also zeroes the LN-stats buffer.
__global__ void __launch_bounds__(256) gemm_qkv6_kernel(
    const float* __restrict__ x_tgt, const float* __restrict__ enc,
    const float* __restrict__ swq, const float* __restrict__ swk,
    const float* __restrict__ swv, const float* __restrict__ cwq,
    const float* __restrict__ cwk, const float* __restrict__ cwv,
    float* __restrict__ q1, float* __restrict__ k1, float* __restrict__ v1,
    float* __restrict__ q2, float* __restrict__ k2, float* __restrict__ v2,
    float2* __restrict__ stats)
{
    const int which = blockIdx.x >> 1;
    const float* A = (which == 3) ? enc : x_tgt;
    const float* W; float* out;
    switch (which) {
        case 0: W = swq; out = q1; break;
        case 1: W = swk; out = k1; break;
        case 2: W = swv; out = v1; break;
        case 3: W = cwq; out = q2; break;
        case 4: W = cwk; out = k2; break;
        default: W = cwv; out = v2; break;
    }

    if (blockIdx.x == 0 && threadIdx.x < 128) {
        ((float*)&stats[blockIdx.y * 64])[threadIdx.x] = 0.f;
    }

    constexpr int WSTR = 72;
    extern __shared__ unsigned smem[];
    unsigned* Ws = smem;                       // [64][72] bf16x2
    float* As = (float*)(smem + 64 * WSTR);
    const unsigned As_sh = (unsigned)__cvta_generic_to_shared(As);
    const int tid = threadIdx.x, warp = tid >> 5, lane = tid & 31;
    const int warp_m = warp >> 1, warp_n = warp & 1;
    const int g = lane >> 2, t = lane & 3;
    const int bm = blockIdx.y * 64, bn = (blockIdx.x & 1) * 64;

    for (int i = tid; i < 64 * 16; i += 256) {
        int p = i / 16, c = (i % 16) * 4;
        float4 wa = *(const float4*)&W[(size_t)(2 * p) * DD + bn + c];
        float4 wb = *(const float4*)&W[(size_t)(2 * p + 1) * DD + bn + c];
        uint4 u = {pack_bf16x2(wa.x, wb.x), pack_bf16x2(wa.y, wb.y),
                   pack_bf16x2(wa.z, wb.z), pack_bf16x2(wa.w, wb.w)};
        *(uint4*)&Ws[p * WSTR + c] = u;
    }

    auto loadA = [&](int kt, int buf) {
        int row = tid >> 2, kc = (tid & 3) * 4;
        cp16(As_sh + (buf * ATILE + row * ASTR + kc) * 4,
             &A[(size_t)(bm + row) * DD + kt * 16 + kc]);
        cp_commit();
    };
    loadA(0, 0);

    float acc[4][4] = {};
    const int ra = warp_m * 16 + g;
    const int noff = warp_n * 32;

    for (int kt = 0; kt < DD / 16; kt++) {
        if (kt + 1 < DD / 16) loadA(kt + 1, (kt + 1) & 1);
        else cp_commit();
        cp_wait1();
        __syncthreads();
        const float* Ab = As + (kt & 1) * ATILE;
        float2 x0 = *(const float2*)&Ab[ra * ASTR + 2 * t];
        float2 x1 = *(const float2*)&Ab[(ra + 8) * ASTR + 2 * t];
        float2 x2 = *(const float2*)&Ab[ra * ASTR + 2 * t + 8];
        float2 x3 = *(const float2*)&Ab[(ra + 8) * ASTR + 2 * t + 8];
        unsigned a0 = pack_bf16x2(x0.x, x0.y);
        unsigned a1 = pack_bf16x2(x1.x, x1.y);
        unsigned a2 = pack_bf16x2(x2.x, x2.y);
        unsigned a3 = pack_bf16x2(x3.x, x3.y);
        const int kp = kt * 8;
#pragma unroll
        for (int j = 0; j < 4; j++) {
            unsigned b0 = Ws[(kp + t) * WSTR + noff + j * 8 + g];
            unsigned b1 = Ws[(kp + t + 4) * WSTR + noff + j * 8 + g];
            mma_bf16(acc[j][0], acc[j][1], acc[j][2], acc[j][3],
                     a0, a1, a2, a3, b0, b1);
        }
        __syncthreads();
    }

    const int r0 = bm + ra;
    const int bb0 = r0 >> 11, ss0 = r0 & (SS - 1);
    const int r1 = r0 + 8;
    const int bb1 = r1 >> 11, ss1 = r1 & (SS - 1);
#pragma unroll
    for (int j = 0; j < 4; j++) {
#pragma unroll
        for (int u = 0; u < 2; u++) {
            int c = bn + noff + j * 8 + 2 * t + u;
            int hh = c & 7, hd = c >> 3;
            out[(((size_t)(bb0 * HH + hh) * SS) + ss0) * HDIM + hd] = acc[j][u];
            out[(((size_t)(bb1 * HH + hh) * SS) + ss1) * HDIM + hd] = acc[j][2 + u];
        }
    }
}

// ---------------- flash attention (both attentions, concat output) ------------
// grid (S/64, B*H, 2): z=0 self -> cols 0-127, z=1 cross -> cols 128-255
// of attn_cat (stride DCAT).  128 thr (4 warps), warp owns 16 query rows.
#define VSTRIDE 136

__global__ void __launch_bounds__(128) attn_mma_kernel(
    const float* __restrict__ q1, const float* __restrict__ k1,
    const float* __restrict__ v1,
    const float* __restrict__ q2, const float* __restrict__ k2,
    const float* __restrict__ v2, float* __restrict__ ocat)
{
    const float* q = blockIdx.z ? q2 : q1;
    const float* k = blockIdx.z ? k2 : k1;
    const float* v = blockIdx.z ? v2 : v1;
    float* out = ocat + (blockIdx.z ? DD : 0);

    __shared__ unsigned Ks[128][8];
    __shared__ __nv_bfloat16 Vs[16][VSTRIDE];
    const int tid = threadIdx.x, w = tid >> 5, lane = tid & 31;
    const int bh = blockIdx.y, b = bh >> 3, h = bh & 7;
    const int g = lane >> 2, c = lane & 3;
    const size_t head = (size_t)bh * SS;
    const int qrow = blockIdx.x * 64 + w * 16;

    const float sc = 0.25f * 1.4426950408889634f;
    unsigned qa[4];
    {
        const float* r0 = q + (head + qrow + g) * HDIM;
        const float* r1 = r0 + 8 * HDIM;
        float2 t;
        t = *(const float2*)(r0 + 2 * c);     qa[0] = pack_bf16x2(t.x * sc, t.y * sc);
        t = *(const float2*)(r1 + 2 * c);     qa[1] = pack_bf16x2(t.x * sc, t.y * sc);
        t = *(const float2*)(r0 + 2 * c + 8); qa[2] = pack_bf16x2(t.x * sc, t.y * sc);
        t = *(const float2*)(r1 + 2 * c + 8); qa[3] = pack_bf16x2(t.x * sc, t.y * sc);
    }

    float o[8] = {0, 0, 0, 0, 0, 0, 0, 0};
    float l0 = 0.f, l1 = 0.f;

    for (int kt = 0; kt < SS / 128; kt++) {
        __syncthreads();
        const float4* ksrc = (const float4*)(k + (head + kt * 128) * HDIM);
        const float4* vsrc = (const float4*)(v + (head + kt * 128) * HDIM);
#pragma unroll
        for (int i = 0; i < 4; i++) {
            int idx = tid + i * 128;
            int key = idx >> 2, f4 = idx & 3;
            float4 t = ksrc[idx];
            Ks[key][f4 * 2]     = pack_bf16x2(t.x, t.y);
            Ks[key][f4 * 2 + 1] = pack_bf16x2(t.z, t.w);
            float4 u = vsrc[idx];
            Vs[f4 * 4 + 0][key] = __float2bfloat16(u.x);
            Vs[f4 * 4 + 1][key] = __float2bfloat16(u.y);
            Vs[f4 * 4 + 2][key] = __float2bfloat16(u.z);
            Vs[f4 * 4 + 3][key] = __float2bfloat16(u.w);
        }
        __syncthreads();

#pragma unroll
        for (int kc = 0; kc < 8; kc++) {
            float s0 = 0, s1 = 0, s2 = 0, s3 = 0, s4 = 0, s5 = 0, s6 = 0, s7 = 0;
            {
                unsigned b0 = Ks[kc * 16 + g][c];
                unsigned b1 = Ks[kc * 16 + g][c + 4];
                mma_bf16(s0, s1, s2, s3, qa[0], qa[1], qa[2], qa[3], b0, b1);
                b0 = Ks[kc * 16 + 8 + g][c];
                b1 = Ks[kc * 16 + 8 + g][c + 4];
                mma_bf16(s4, s5, s6, s7, qa[0], qa[1], qa[2], qa[3], b0, b1);
            }
            float p0 = ex2(s0), p1 = ex2(s1), p2 = ex2(s2), p3 = ex2(s3);
            float p4 = ex2(s4), p5 = ex2(s5), p6 = ex2(s6), p7 = ex2(s7);
            l0 += (p0 + p1) + (p4 + p5);
            l1 += (p2 + p3) + (p6 + p7);
            unsigned A0 = pack_bf16x2(p0, p1);
            unsigned A1 = pack_bf16x2(p2, p3);
            unsigned A2 = pack_bf16x2(p4, p5);
            unsigned A3 = pack_bf16x2(p6, p7);
            unsigned vb0 = *(const unsigned*)&Vs[g][kc * 16 + 2 * c];
            unsigned vb1 = *(const unsigned*)&Vs[g][kc * 16 + 2 * c + 8];
            mma_bf16(o[0], o[1], o[2], o[3], A0, A1, A2, A3, vb0, vb1);
            vb0 = *(const unsigned*)&Vs[8 + g][kc * 16 + 2 * c];
            vb1 = *(const unsigned*)&Vs[8 + g][kc * 16 + 2 * c + 8];
            mma_bf16(o[4], o[5], o[6], o[7], A0, A1, A2, A3, vb0, vb1);
        }
    }

    l0 += __shfl_xor_sync(~0u, l0, 1); l0 += __shfl_xor_sync(~0u, l0, 2);
    l1 += __shfl_xor_sync(~0u, l1, 1); l1 += __shfl_xor_sync(~0u, l1, 2);
    const float inv0 = 1.0f / l0, inv1 = 1.0f / l1;

    float* ob0 = out + ((size_t)(b * SS) + qrow + g) * DCAT + h;
    float* ob1 = out + ((size_t)(b * SS) + qrow + 8 + g) * DCAT + h;
    ob0[(2 * c) * HH]     = o[0] * inv0;
    ob0[(2 * c + 1) * HH] = o[1] * inv0;
    ob0[(8 + 2 * c) * HH] = o[4] * inv0;
    ob0[(9 + 2 * c) * HH] = o[5] * inv0;
    ob1[(2 * c) * HH]     = o[2] * inv1;
    ob1[(2 * c + 1) * HH] = o[3] * inv1;
    ob1[(8 + 2 * c) * HH] = o[6] * inv1;
    ob1[(9 + 2 * c) * HH] = o[7] * inv1;
}

// ---------------- launch --------------------------------------------------------
extern "C" void kernel_launch(void* const* d_in, const int* in_sizes, int n_in,
                              void* d_out, int out_size) {
    (void)in_sizes; (void)n_in; (void)out_size;
    const float* x_tgt = (const float*)d_in[0];
    const float* enc   = (const float*)d_in[1];
    const float* swq   = (const float*)d_in[2];
    const float* swk   = (const float*)d_in[3];
    const float* swv   = (const float*)d_in[4];
    const float* cwq   = (const float*)d_in[5];
    const float* cwk   = (const float*)d_in[6];
    const float* cwv   = (const float*)d_in[7];
    const float* w1    = (const float*)d_in[8];
    const float* b1    = (const float*)d_in[9];
    const float* w2    = (const float*)d_in[10];
    const float* b2    = (const float*)d_in[11];
    const float* w3    = (const float*)d_in[12];
    const float* b3    = (const float*)d_in[13];
    const float* w4    = (const float*)d_in[14];
    const float* b4    = (const float*)d_in[15];
    float* out = (float*)d_out;

    float *q1, *k1, *v1, *q2, *k2, *v2, *acat, *r2, *h;
    float2* st;
    cudaGetSymbolAddress((void**)&q1,   g_q1);
    cudaGetSymbolAddress((void**)&k1,   g_k1);
    cudaGetSymbolAddress((void**)&v1,   g_v1);
    cudaGetSymbolAddress((void**)&q2,   g_q2);
    cudaGetSymbolAddress((void**)&k2,   g_k2);
    cudaGetSymbolAddress((void**)&v2,   g_v2);
    cudaGetSymbolAddress((void**)&acat, g_attn_cat);
    cudaGetSymbolAddress((void**)&r2,   g_r2);
    cudaGetSymbolAddress((void**)&st,   g_stats);
    cudaGetSymbolAddress((void**)&h,    g_h);

    // dynamic smem: W panel + 2 A stages
    const int smQKV = 64 * 72 * 4 + 2 * ATILE * 4;     // 18432+10240 = 28672
    const int smR2  = 256 * 40 * 4 + 2 * ATILE * 4;    // 51200 -> attribute
    const int smW3  = 64 * 72 * 4 + 2 * ATILE * 4;     // 28672
    const int smW4  = 256 * 40 * 4 + 2 * ATILE * 4;    // 51200 -> attribute
    cudaFuncSetAttribute(gemm_r2_kernel<256, 128, 32>,
                         cudaFuncAttributeMaxDynamicSharedMemorySize, smR2);
    cudaFuncSetAttribute(gemm_bf16_kernel<512, 128, 32, 1, 0>,
                         cudaFuncAttributeMaxDynamicSharedMemorySize, smW4);

    const dim3 gQKV(12, MROWS / 64);              // all six projections
    const dim3 gA(SS / 64, BB * HH, 2);           // both attentions
    const dim3 gR2(4, MROWS / 64);                // fused r2 (K=256) + stats
    const dim3 gW3(8, MROWS / 64);                // N=512, BN=64, LN-apply
    const dim3 gW4(4, MROWS / 64);                // K=512 -> N=128

    gemm_qkv6_kernel<<<gQKV, 256, smQKV>>>(x_tgt, enc, swq, swk, swv,
                                           cwq, cwk, cwv,
                                           q1, k1, v1, q2, k2, v2, st);
    attn_mma_kernel<<<gA, 128>>>(q1, k1, v1, q2, k2, v2, acat);
    // r2 = [attn1|attn2] @ [w1;w2] + b1 + b2 + x_tgt (tf32 — precision path)
    gemm_r2_kernel<256, 128, 32><<<gR2, 256, smR2>>>(
        acat, w1, w2, b1, b2, x_tgt, st, r2);
    // h = relu(ln(r2) @ w3 + b3), LN applied at fragment load (bf16 mma)
    gemm_bf16_kernel<128, 512, 64, 2, 1><<<gW3, 256, smW3>>>(
        r2, w3, b3, nullptr, st, h);
    // out = h @ w4 + b4 + r2 (bf16 mma)
    gemm_bf16_kernel<512, 128, 32, 1, 0><<<gW4, 256, smW4>>>(
        h, w4, b4, r2, nullptr, out);
}